// round 2
// baseline (speedup 1.0000x reference)
#include <cuda_runtime.h>
#include <cuda_bf16.h>

// LayerNorm over last dim W=256 for input (B=8, C=128, H=128, W=256) fp32,
// then per-channel affine.
//
// 2 rows per warp, all 4 LDG.128 front-batched for MLP. Independent
// warp-shuffle reductions for the two rows pipeline through the SHFL unit.

#define EPS 1e-8f
#define W_DIM 256
#define H_DIM 128
#define C_DIM 128
#define ROWS_PER_WARP 2
#define WARPS_PER_BLOCK 8
#define ROWS_PER_BLOCK (ROWS_PER_WARP * WARPS_PER_BLOCK)

__global__ __launch_bounds__(256, 8)
void ln_warp2_kernel(const float* __restrict__ inp,
                     const float* __restrict__ gain,
                     const float* __restrict__ bias,
                     float* __restrict__ out,
                     int n_rows)
{
    const int warp_in_block = threadIdx.x >> 5;
    const int lane = threadIdx.x & 31;
    const int row0 = blockIdx.x * ROWS_PER_BLOCK + warp_in_block * ROWS_PER_WARP;

    const float4* in4  = reinterpret_cast<const float4*>(inp);
    float4*       out4 = reinterpret_cast<float4*>(out);

    // 64 float4 per row
    const size_t base_a = (size_t)row0 * 64 + lane * 2;
    const size_t base_b = base_a + 64;

    // Front-batch all 4 independent 128-bit loads (streaming: no reuse).
    float4 a0 = __ldcs(&in4[base_a + 0]);
    float4 a1 = __ldcs(&in4[base_a + 1]);
    float4 b0 = __ldcs(&in4[base_b + 0]);
    float4 b1 = __ldcs(&in4[base_b + 1]);

    float sa  = a0.x + a0.y + a0.z + a0.w + a1.x + a1.y + a1.z + a1.w;
    float ssa = a0.x*a0.x + a0.y*a0.y + a0.z*a0.z + a0.w*a0.w
              + a1.x*a1.x + a1.y*a1.y + a1.z*a1.z + a1.w*a1.w;
    float sb  = b0.x + b0.y + b0.z + b0.w + b1.x + b1.y + b1.z + b1.w;
    float ssb = b0.x*b0.x + b0.y*b0.y + b0.z*b0.z + b0.w*b0.w
              + b1.x*b1.x + b1.y*b1.y + b1.z*b1.z + b1.w*b1.w;

    // Two independent warp reductions -> shuffles pipeline.
    #pragma unroll
    for (int off = 16; off > 0; off >>= 1) {
        sa  += __shfl_xor_sync(0xFFFFFFFFu, sa,  off);
        sb  += __shfl_xor_sync(0xFFFFFFFFu, sb,  off);
        ssa += __shfl_xor_sync(0xFFFFFFFFu, ssa, off);
        ssb += __shfl_xor_sync(0xFFFFFFFFu, ssb, off);
    }

    const float inv_w = 1.0f / (float)W_DIM;
    float mean_a = sa * inv_w;
    float var_a  = ssa * inv_w - mean_a * mean_a;
    float rstd_a = rsqrtf(var_a + EPS);
    float mean_b = sb * inv_w;
    float var_b  = ssb * inv_w - mean_b * mean_b;
    float rstd_b = rsqrtf(var_b + EPS);

    // channel: row = ((b*C + c)*H + h) -> c = (row >> 7) & 127
    int ca = ((row0 + 0) >> 7) & (C_DIM - 1);
    int cb = ((row0 + 1) >> 7) & (C_DIM - 1);
    float ga = __ldg(gain + ca), ba = __ldg(bias + ca);
    float gb = __ldg(gain + cb), bb = __ldg(bias + cb);

    float sc_a = rstd_a * ga, sh_a = ba - mean_a * rstd_a * ga;
    float sc_b = rstd_b * gb, sh_b = bb - mean_b * rstd_b * gb;

    a0.x = a0.x * sc_a + sh_a;  a0.y = a0.y * sc_a + sh_a;
    a0.z = a0.z * sc_a + sh_a;  a0.w = a0.w * sc_a + sh_a;
    a1.x = a1.x * sc_a + sh_a;  a1.y = a1.y * sc_a + sh_a;
    a1.z = a1.z * sc_a + sh_a;  a1.w = a1.w * sc_a + sh_a;
    b0.x = b0.x * sc_b + sh_b;  b0.y = b0.y * sc_b + sh_b;
    b0.z = b0.z * sc_b + sh_b;  b0.w = b0.w * sc_b + sh_b;
    b1.x = b1.x * sc_b + sh_b;  b1.y = b1.y * sc_b + sh_b;
    b1.z = b1.z * sc_b + sh_b;  b1.w = b1.w * sc_b + sh_b;

    __stcs(&out4[base_a + 0], a0);
    __stcs(&out4[base_a + 1], a1);
    __stcs(&out4[base_b + 0], b0);
    __stcs(&out4[base_b + 1], b1);
}

extern "C" void kernel_launch(void* const* d_in, const int* in_sizes, int n_in,
                              void* d_out, int out_size) {
    const float* inp  = (const float*)d_in[0];
    const float* gain = (const float*)d_in[1];
    const float* bias = (const float*)d_in[2];
    float* out = (float*)d_out;

    int n_rows = in_sizes[0] / W_DIM;            // 131072
    int blocks = n_rows / ROWS_PER_BLOCK;        // 8192 (exact: 131072/16)

    ln_warp2_kernel<<<blocks, 256>>>(inp, gain, bias, out, n_rows);
}